// round 16
// baseline (speedup 1.0000x reference)
#include <cuda_runtime.h>
#include <cfloat>

#define Nn 20000
#define Ee 320000
#define Gg 64
#define D0 16
#define Hh 32
#define NK 33
#define EPSI 1e-5f
#define FULL 0xffffffffu
#define TPB 1024
#define NZ 8
#define ZN (Nn/NZ)      /* 2500 */

// ---------------- static device scratch (zero-init at load; self-cleaning across replays) ----------------
__device__ float g_A0[NK*D0*Hh], g_B0[NK*D0*Hh];
__device__ float g_A1[NK*Hh*Hh], g_B1[NK*Hh*Hh];
__device__ int g_deg[Nn];               // zeroed in alloc phase after read
__device__ int g_rank[Ee];              // per-edge rank within its dst segment
__device__ int g_total;                 // zeroed in final phase each run
__device__ int g_off[Nn], g_end[Nn];
__device__ int g_nlive[2], g_klive[2];
__device__ int g_work[2*NZ];            // work-stealing counters, zeroed in P1 each run
__device__ float g_bmin[1024], g_bmax[1024];
__device__ uint2 g_ebuf[Ee];
__device__ __align__(16) float g_PQ[(size_t)NK*Nn*64];   // general path only
__device__ __align__(16) float g_h[Nn*Hh], g_hn[Nn*Hh];
__device__ float g_stats[4*Hh];
__device__ float g_pool[Gg*Hh];
__device__ int   g_pcnt[Gg];
__device__ int g_bcnt[8];
__device__ volatile int g_bsense[8];

__device__ __forceinline__ void gridbar(int i){
    __syncthreads();
    if (threadIdx.x == 0){
        int sense = g_bsense[i];
        __threadfence();
        if (atomicAdd(&g_bcnt[i], 1) == (int)gridDim.x - 1){
            g_bcnt[i] = 0;
            __threadfence();
            g_bsense[i] = sense ^ 1;
        } else {
            while (g_bsense[i] == sense) __nanosleep(64);
            __threadfence();
        }
    }
    __syncthreads();
}

__device__ __forceinline__ void rank32(float wj, float bj, float& t, int& r, int j){
    t = (wj != 0.0f) ? (-bj / wj) : FLT_MAX;
    r = 0;
    #pragma unroll
    for (int m = 0; m < 32; m++){
        float tm = __shfl_sync(FULL, t, m);
        r += (tm < t || (tm == t && m < j));
    }
}

// ==== aggregation phase: fast path = work-stealing + rolling prefetch ====
template<int DIN, int LAYER>
__device__ __forceinline__ void agg_phase(
    const float* __restrict__ xin, const float* __restrict__ root,
    const float* __restrict__ bias, float* __restrict__ hout,
    float* sA, float* sB, float* sR, float* sBi,
    float* ssum, float* ssq, float (*sAcc)[64], int nlive, int kl)
{
    constexpr int NC = DIN/4;
    constexpr int NS = 32/NC;
    int t = threadIdx.x, lane = t & 31, w = t >> 5;
    __syncthreads();
    if (t < 32){ ssum[t] = 0.f; ssq[t] = 0.f; sBi[t] = __ldg(bias + t); }
    for (int d = t; d < DIN*32; d += TPB) sR[d] = __ldg(root + d);
    if (nlive == 1){
        const float* A = LAYER ? g_A1 : g_A0;
        const float* B = LAYER ? g_B1 : g_B0;
        for (int d = t; d < DIN*32; d += TPB){
            sA[d] = A[kl*DIN*32 + d];
            sB[d] = B[kl*DIN*32 + d];
        }
    }
    __syncthreads();

    const float4* x4 = (const float4*)xin;
    float accS = 0.f, accQ = 0.f;

    if (nlive == 1){
        int slot = lane / NC, c = lane % NC;
        int z = (blockIdx.x*32 + w) & (NZ-1);
        int* cnt = &g_work[LAYER*NZ + z];
        int zb = z*ZN;

        // prefetched next-node state (filled by donode while reducing current)
        int ps = 0, pe = 0;
        bool pf0 = false, pf1 = false;
        uint2 pp0 = make_uint2(0,0), pp1 = make_uint2(0,0);

        auto donode = [&](int v, int s, int e1, bool f0, bool f1, uint2 q0, uint2 q1, int pv){
            float4 ya0={0,0,0,0}, yb0={0,0,0,0}, ya1={0,0,0,0}, yb1={0,0,0,0};
            int c0 = s + slot, c1 = c0 + NS;
            while (__any_sync(FULL, f0)){
                int n0 = c0 + 2*NS, n1 = c1 + 2*NS;
                bool w0 = n0 < e1, w1 = n1 < e1;
                uint2 r0 = make_uint2(0,0), r1 = make_uint2(0,0);
                if (w0) r0 = __ldcg(&g_ebuf[n0]);
                if (w1) r1 = __ldcg(&g_ebuf[n1]);
                if (f0){
                    int u = q0.x & 0xFFFF; float a = __uint_as_float(q0.y);
                    float4 xc = x4[(size_t)u*NC + c];
                    ya0.x = fmaf(a, xc.x, ya0.x); yb0.x += xc.x;
                    ya0.y = fmaf(a, xc.y, ya0.y); yb0.y += xc.y;
                    ya0.z = fmaf(a, xc.z, ya0.z); yb0.z += xc.z;
                    ya0.w = fmaf(a, xc.w, ya0.w); yb0.w += xc.w;
                }
                if (f1){
                    int u = q1.x & 0xFFFF; float a = __uint_as_float(q1.y);
                    float4 xc = x4[(size_t)u*NC + c];
                    ya1.x = fmaf(a, xc.x, ya1.x); yb1.x += xc.x;
                    ya1.y = fmaf(a, xc.y, ya1.y); yb1.y += xc.y;
                    ya1.z = fmaf(a, xc.z, ya1.z); yb1.z += xc.z;
                    ya1.w = fmaf(a, xc.w, ya1.w); yb1.w += xc.w;
                }
                c0 = n0; c1 = n1; f0 = w0; f1 = w1; q0 = r0; q1 = r1;
            }
            // prefetch next node's bounds + first payloads (hidden behind reduce/epilogue)
            if (pv >= 0){
                ps = g_off[pv]; pe = g_end[pv];
                int i0 = ps + slot, i1 = i0 + NS;
                pf0 = i0 < pe; pf1 = i1 < pe;
                if (pf0) pp0 = __ldcg(&g_ebuf[i0]);
                if (pf1) pp1 = __ldcg(&g_ebuf[i1]);
            }
            float4 ya, yb;
            ya.x = ya0.x + ya1.x; ya.y = ya0.y + ya1.y;
            ya.z = ya0.z + ya1.z; ya.w = ya0.w + ya1.w;
            yb.x = yb0.x + yb1.x; yb.y = yb0.y + yb1.y;
            yb.z = yb0.z + yb1.z; yb.w = yb0.w + yb1.w;
            #pragma unroll
            for (int off = NC; off < 32; off <<= 1){
                ya.x += __shfl_xor_sync(FULL, ya.x, off);
                ya.y += __shfl_xor_sync(FULL, ya.y, off);
                ya.z += __shfl_xor_sync(FULL, ya.z, off);
                ya.w += __shfl_xor_sync(FULL, ya.w, off);
                yb.x += __shfl_xor_sync(FULL, yb.x, off);
                yb.y += __shfl_xor_sync(FULL, yb.y, off);
                yb.z += __shfl_xor_sync(FULL, yb.z, off);
                yb.w += __shfl_xor_sync(FULL, yb.w, off);
            }
            if (lane < NC){
                int f = lane*4;
                sAcc[w][f+0] = ya.x; sAcc[w][f+1] = ya.y;
                sAcc[w][f+2] = ya.z; sAcc[w][f+3] = ya.w;
                sAcc[w][DIN+f+0] = yb.x; sAcc[w][DIN+f+1] = yb.y;
                sAcc[w][DIN+f+2] = yb.z; sAcc[w][DIN+f+3] = yb.w;
            }
            __syncwarp();
            float msg = 0.f;
            #pragma unroll
            for (int i = 0; i < DIN; i++){
                msg = fmaf(sAcc[w][i],     sA[i*32+lane], msg);
                msg = fmaf(sAcc[w][DIN+i], sB[i*32+lane], msg);
            }
            float inv = 1.f / fmaxf((float)(e1 - s), 1.f);
            float xv = (lane < DIN) ? xin[(size_t)v*DIN + lane] : 0.f;
            float rt = 0.f;
            #pragma unroll
            for (int i = 0; i < DIN; i++)
                rt = fmaf(__shfl_sync(FULL, xv, i), sR[i*32+lane], rt);
            float o = rt + msg*inv + sBi[lane];
            hout[(size_t)v*32 + lane] = o;
            accS += o;
            accQ = fmaf(o, o, accQ);
        };

        // work-stealing loop with grab-ahead: next pair's atomic issued a node early
        int g0 = 0;
        if (lane == 0) g0 = atomicAdd(cnt, 2);
        g0 = __shfl_sync(FULL, g0, 0);
        int v    = (g0     < ZN) ? zb + g0     : Nn;
        int vnxt = (g0 + 1 < ZN) ? zb + g0 + 1 : Nn;
        int gnext = 0;
        if (lane == 0) gnext = atomicAdd(cnt, 2);   // in flight
        int s = 0, e1 = 0;
        bool f0 = false, f1 = false;
        uint2 q0 = make_uint2(0,0), q1 = make_uint2(0,0);
        if (v < Nn){
            s = g_off[v]; e1 = g_end[v];
            int i0 = s + slot, i1 = i0 + NS;
            f0 = i0 < e1; f1 = i1 < e1;
            if (f0) q0 = __ldcg(&g_ebuf[i0]);
            if (f1) q1 = __ldcg(&g_ebuf[i1]);
        }
        while (v < Nn){
            int pv = vnxt;
            if (pv >= Nn){
                int g = __shfl_sync(FULL, gnext, 0);   // resolve grab issued a node ago
                pv   = (g     < ZN) ? zb + g     : Nn;
                vnxt = (g + 1 < ZN) ? zb + g + 1 : Nn;
                if (lane == 0) gnext = atomicAdd(cnt, 2);   // re-arm
            } else {
                vnxt = Nn;   // consumed the pair partner
            }
            donode(v, s, e1, f0, f1, q0, q1, (pv < Nn) ? pv : -1);
            v = pv; s = ps; e1 = pe; f0 = pf0; f1 = pf1; q0 = pp0; q1 = pp1;
        }
    } else {
        int slot = lane >> 3, c = lane & 7;
        int shift = 16 + (LAYER << 3);
        for (int v = blockIdx.x*32 + w; v < Nn; v += gridDim.x*32){
            int s = g_off[v], e1 = g_end[v];
            float4 acc = {0,0,0,0};
            for (int base = s; base < e1; base += 4){
                int i = base + slot;
                if (i < e1){
                    uint2 pl = __ldcg(&g_ebuf[i]);
                    int u = pl.x & 0xFFFF; int kk = (pl.x >> shift) & 0xFF;
                    float a = __uint_as_float(pl.y);
                    const float4* row = (const float4*)(g_PQ + ((size_t)(kk*Nn + u))*64);
                    float4 p = row[c], q = row[8+c];
                    acc.x = fmaf(a, p.x, acc.x) + q.x;
                    acc.y = fmaf(a, p.y, acc.y) + q.y;
                    acc.z = fmaf(a, p.z, acc.z) + q.z;
                    acc.w = fmaf(a, p.w, acc.w) + q.w;
                }
            }
            #pragma unroll
            for (int off = 8; off < 32; off <<= 1){
                acc.x += __shfl_xor_sync(FULL, acc.x, off);
                acc.y += __shfl_xor_sync(FULL, acc.y, off);
                acc.z += __shfl_xor_sync(FULL, acc.z, off);
                acc.w += __shfl_xor_sync(FULL, acc.w, off);
            }
            if (lane < 8){
                int f = lane*4;
                sAcc[w][f+0] = acc.x; sAcc[w][f+1] = acc.y;
                sAcc[w][f+2] = acc.z; sAcc[w][f+3] = acc.w;
            }
            __syncwarp();
            float msg = sAcc[w][lane];
            float inv = 1.f / fmaxf((float)(e1 - s), 1.f);
            float xv = (lane < DIN) ? xin[(size_t)v*DIN + lane] : 0.f;
            float rt = 0.f;
            #pragma unroll
            for (int i = 0; i < DIN; i++)
                rt = fmaf(__shfl_sync(FULL, xv, i), sR[i*32+lane], rt);
            float o = rt + msg*inv + sBi[lane];
            hout[(size_t)v*32 + lane] = o;
            accS += o;
            accQ = fmaf(o, o, accQ);
        }
    }
    atomicAdd(&ssum[lane], accS);
    atomicAdd(&ssq[lane], accQ);
    __syncthreads();
    if (t < 32){
        atomicAdd(&g_stats[LAYER*64 + t],      ssum[t]);
        atomicAdd(&g_stats[LAYER*64 + 32 + t], ssq[t]);
    }
}

// ==== single persistent mega-kernel ====
__global__ void __launch_bounds__(TPB, 1)
k_mega(const float* __restrict__ x, const float* __restrict__ attr,
       const float* __restrict__ edft, const int* __restrict__ src,
       const int* __restrict__ dst, const int* __restrict__ batch,
       const float* l0w1, const float* l0b1, const float* l0w2, const float* l0b2,
       const float* l0root, const float* l0bias, const float* l0g, const float* l0be,
       const float* l1w1, const float* l1b1, const float* l1w2, const float* l1b2,
       const float* l1root, const float* l1bias, const float* l1g, const float* l1be,
       const float* mw1, const float* mb1, const float* mw2, const float* mb2,
       float* out)
{
    __shared__ float sW0[1024], sW1[1024], sW2[1024];
    __shared__ float sSc[32], sSh[32], sBi[32], ssum[32], ssq[32];
    __shared__ float sMin[32], sMax[32];
    __shared__ float sAcc[32][64];
    int t = threadIdx.x, lane = t & 31, w = t >> 5;

    // -------- P0: zeroing (block 0) + buildAB (blocks <2NK) + edge deg/rank/minmax (all) --------
    if (blockIdx.x == 0){
        for (int i = t; i < 4*Hh; i += TPB) g_stats[i] = 0.f;
        for (int i = t; i < Gg*Hh; i += TPB) g_pool[i] = 0.f;
        if (t < Gg) g_pcnt[t] = 0;
    }
    if (blockIdx.x < 2*NK){
        int layer = (blockIdx.x >= NK);
        int k = blockIdx.x - layer*NK;
        int D = layer ? (Hh*Hh) : (D0*Hh);
        float* A = layer ? g_A1 : g_A0;
        float* B = layer ? g_B1 : g_B0;
        const float* ew1 = layer ? l1w1 : l0w1;
        const float* eb1 = layer ? l1b1 : l0b1;
        const float* ew2 = layer ? l1w2 : l0w2;
        const float* eb2 = layer ? l1b2 : l0b2;
        float* sw = sW0; float* sb = sW0 + 32; int* sr = (int*)sW1;
        if (t < 32){
            float wj = ew1[t], bj = eb1[t], tv; int r;
            rank32(wj, bj, tv, r, t);
            sw[t] = wj; sb[t] = bj; sr[t] = r;
        }
        __syncthreads();
        for (int d = t; d < D; d += TPB){
            float a = 0.f, b = eb2[d];
            for (int j = 0; j < 32; j++){
                float wj = sw[j];
                bool act = (wj > 0.f) ? (k > sr[j]) : ((wj < 0.f) ? (k <= sr[j]) : (sb[j] > 0.f));
                if (act){ float w2 = ew2[j*D+d]; a += wj*w2; b += sb[j]*w2; }
            }
            A[k*D+d] = a; B[k*D+d] = b;
        }
        __syncthreads();
    }
    {
        float amn = FLT_MAX, amx = -FLT_MAX;
        for (int e = blockIdx.x*TPB + t; e < Ee; e += gridDim.x*TPB){
            float a = attr[e];
            amn = fminf(amn, a); amx = fmaxf(amx, a);
            g_rank[e] = atomicAdd(&g_deg[dst[e]], 1);
        }
        #pragma unroll
        for (int off = 16; off; off >>= 1){
            amn = fminf(amn, __shfl_xor_sync(FULL, amn, off));
            amx = fmaxf(amx, __shfl_xor_sync(FULL, amx, off));
        }
        if (lane == 0){ sMin[w] = amn; sMax[w] = amx; }
        __syncthreads();
        if (t < 32){
            amn = sMin[t]; amx = sMax[t];
            #pragma unroll
            for (int off = 16; off; off >>= 1){
                amn = fminf(amn, __shfl_xor_sync(FULL, amn, off));
                amx = fmaxf(amx, __shfl_xor_sync(FULL, amx, off));
            }
            if (t == 0){ g_bmin[blockIdx.x] = amn; g_bmax[blockIdx.x] = amx; }
        }
    }
    gridbar(0);

    // -------- P1: segment allocation + interval-range detect + work-counter zero --------
    if (blockIdx.x == 0 && t >= 32 && t < 32 + 2*NZ) g_work[t - 32] = 0;
    if (blockIdx.x == 0 && t < 32){
        float amn = FLT_MAX, amx = -FLT_MAX;
        for (int b = lane; b < (int)gridDim.x; b += 32){
            amn = fminf(amn, g_bmin[b]); amx = fmaxf(amx, g_bmax[b]);
        }
        #pragma unroll
        for (int off = 16; off; off >>= 1){
            amn = fminf(amn, __shfl_xor_sync(FULL, amn, off));
            amx = fmaxf(amx, __shfl_xor_sync(FULL, amx, off));
        }
        float wj = l0w1[lane], bj = l0b1[lane];
        float tj = (wj != 0.f) ? (-bj/wj) : FLT_MAX;
        int kmin = __popc(__ballot_sync(FULL, tj <= amn));
        int kmax = __popc(__ballot_sync(FULL, tj <= amx));
        if (lane == 0){ g_klive[0] = kmin; g_nlive[0] = kmax - kmin + 1; }
        wj = l1w1[lane]; bj = l1b1[lane];
        tj = (wj != 0.f) ? (-bj/wj) : FLT_MAX;
        kmin = __popc(__ballot_sync(FULL, tj <= amn));
        kmax = __popc(__ballot_sync(FULL, tj <= amx));
        if (lane == 0){ g_klive[1] = kmin; g_nlive[1] = kmax - kmin + 1; }
    }
    for (int base = blockIdx.x*TPB; base < Nn; base += gridDim.x*TPB){
        int i = base + t;
        int d = (i < Nn) ? g_deg[i] : 0;
        int sc = d;
        #pragma unroll
        for (int off = 1; off < 32; off <<= 1){
            int y = __shfl_up_sync(FULL, sc, off);
            if (lane >= off) sc += y;
        }
        int tot = __shfl_sync(FULL, sc, 31);
        int base2 = 0;
        if (lane == 31 && tot) base2 = atomicAdd(&g_total, tot);
        base2 = __shfl_sync(FULL, base2, 31);
        if (i < Nn){
            int my = base2 + sc - d;
            g_off[i] = my; g_end[i] = my + d;
            g_deg[i] = 0;
        }
    }
    gridbar(1);

    int nl0 = g_nlive[0], kl0 = g_klive[0];
    int nl1 = g_nlive[1], kl1 = g_klive[1];
    bool fastboth = (nl0 == 1) && (nl1 == 1);

    // -------- P2: CSR fill (rank-based) + PQ0 (general) --------
    if (!fastboth){
        float* st0 = sW0; float* st1 = sW0 + 32;
        if (t < 32){ float tv; int r; rank32(l0w1[t], l0b1[t], tv, r, t); st0[r] = tv; }
        else if (t < 64){ int j = t-32; float tv; int r; rank32(l1w1[j], l1b1[j], tv, r, j); st1[r] = tv; }
        __syncthreads();
    }
    for (int e = blockIdx.x*TPB + t; e < Ee; e += gridDim.x*TPB){
        float a = attr[e];
        unsigned px = (unsigned)src[e];
        if (!fastboth){
            const float* st0 = sW0; const float* st1 = sW0 + 32;
            int k0 = 0, k1 = 0;
            #pragma unroll
            for (int step = 16; step > 0; step >>= 1){
                if (st0[k0 + step - 1] <= a) k0 += step;
                if (st1[k1 + step - 1] <= a) k1 += step;
            }
            k0 += (st0[k0] <= a);
            k1 += (st1[k1] <= a);
            px |= ((unsigned)k0 << 16) | ((unsigned)k1 << 24);
        }
        uint2 pl; pl.x = px; pl.y = __float_as_uint(a);
        int p = g_off[dst[e]] + g_rank[e];
        g_ebuf[p] = pl;
    }
    if (nl0 > 1){
        for (int u = blockIdx.x*32 + w; u < Nn; u += gridDim.x*32){
            float xv_l = (lane < D0) ? __ldg(x + (size_t)u*D0 + lane) : 0.f;
            for (int k = kl0; k < kl0 + nl0; k++){
                float p = 0.f, q = 0.f;
                for (int i = 0; i < D0; i++){
                    float xv = __shfl_sync(FULL, xv_l, i);
                    p = fmaf(xv, g_A0[k*D0*Hh + i*Hh + lane], p);
                    q = fmaf(xv, g_B0[k*D0*Hh + i*Hh + lane], q);
                }
                size_t ro = ((size_t)(k*Nn + u))*64;
                g_PQ[ro + lane] = p;
                g_PQ[ro + 32 + lane] = q;
            }
        }
    }
    gridbar(2);

    // -------- P3: aggregation layer 0 --------
    agg_phase<D0,0>(x, l0root, l0bias, g_h,
                    sW0, sW1, sW2, sBi, ssum, ssq, sAcc, nl0, kl0);
    gridbar(3);

    // -------- P3a: hn = relu(BN0(h)) once --------
    __syncthreads();
    if (t < 32){
        float mu  = __ldcg(&g_stats[t])    * (1.f/(float)Nn);
        float var = __ldcg(&g_stats[32+t]) * (1.f/(float)Nn) - mu*mu;
        float sc  = rsqrtf(var + EPSI) * __ldg(l0g + t);
        sSc[t] = sc;
        sSh[t] = __ldg(l0be + t) - mu*sc;
    }
    __syncthreads();
    for (int idx = blockIdx.x*TPB + t; idx < Nn*Hh; idx += gridDim.x*TPB){
        int f = idx & 31;
        g_hn[idx] = fmaxf(g_h[idx]*sSc[f] + sSh[f], 0.f);
    }
    gridbar(4);
    if (nl1 > 1){
        for (int u = blockIdx.x*32 + w; u < Nn; u += gridDim.x*32){
            float xv_l = g_hn[(size_t)u*32 + lane];
            for (int k = kl1; k < kl1 + nl1; k++){
                float p = 0.f, q = 0.f;
                for (int i = 0; i < Hh; i++){
                    float xv = __shfl_sync(FULL, xv_l, i);
                    p = fmaf(xv, g_A1[k*Hh*Hh + i*Hh + lane], p);
                    q = fmaf(xv, g_B1[k*Hh*Hh + i*Hh + lane], q);
                }
                size_t ro = ((size_t)(k*Nn + u))*64;
                g_PQ[ro + lane] = p;
                g_PQ[ro + 32 + lane] = q;
            }
        }
        gridbar(5);
    }

    // -------- P4: aggregation layer 1 --------
    agg_phase<Hh,1>(g_hn, l1root, l1bias, g_h,
                    sW0, sW1, sW2, sBi, ssum, ssq, sAcc, nl1, kl1);
    gridbar(6);

    // -------- P5: BN1 + ReLU + pool --------
    __syncthreads();
    if (t < 32){
        float mu  = __ldcg(&g_stats[64+t]) * (1.f/(float)Nn);
        float var = __ldcg(&g_stats[96+t]) * (1.f/(float)Nn) - mu*mu;
        float sc  = rsqrtf(var + EPSI) * __ldg(l1g + t);
        sSc[t] = sc;
        sSh[t] = __ldg(l1be + t) - mu*sc;
    }
    __syncthreads();
    for (int idx = blockIdx.x*TPB + t; idx < Nn*Hh; idx += gridDim.x*TPB){
        int f = idx & 31, v = idx >> 5;
        float xv = fmaxf(g_h[idx]*sSc[f] + sSh[f], 0.f);
        int g = batch[v];
        atomicAdd(&g_pool[g*Hh + f], xv);
        if (f == 0) atomicAdd(&g_pcnt[g], 1);
    }
    gridbar(7);

    // -------- P6: readout MLP + cleanup (block 0) --------
    if (blockIdx.x == 0){
        if (t == TPB-1) g_total = 0;
        if (t < Gg){
            float zin[Hh+1];
            float inv = 1.f / fmaxf((float)__ldcg(&g_pcnt[t]), 1.f);
            for (int i = 0; i < Hh; i++) zin[i] = __ldcg(&g_pool[t*Hh+i])*inv;
            zin[Hh] = edft[t];
            float o = mb2[0];
            for (int j = 0; j < 64; j++){
                float hsum = mb1[j];
                #pragma unroll
                for (int i = 0; i < Hh+1; i++) hsum = fmaf(zin[i], mw1[i*64+j], hsum);
                o = fmaf(fmaxf(hsum, 0.f), mw2[j], o);
            }
            out[t] = o;
        }
    }
}

extern "C" void kernel_launch(void* const* d_in, const int* in_sizes, int n_in,
                              void* d_out, int out_size){
    const float* x     = (const float*)d_in[0];
    const float* attr  = (const float*)d_in[1];
    const float* edft  = (const float*)d_in[2];
    const int*   src   = (const int*)  d_in[3];
    const int*   dst   = (const int*)  d_in[4];
    const int*   batch = (const int*)  d_in[5];
    const float* l0w1=(const float*)d_in[6],  *l0b1=(const float*)d_in[7];
    const float* l0w2=(const float*)d_in[8],  *l0b2=(const float*)d_in[9];
    const float* l0root=(const float*)d_in[10],*l0bias=(const float*)d_in[11];
    const float* l0g=(const float*)d_in[12],  *l0be=(const float*)d_in[13];
    const float* l1w1=(const float*)d_in[14], *l1b1=(const float*)d_in[15];
    const float* l1w2=(const float*)d_in[16], *l1b2=(const float*)d_in[17];
    const float* l1root=(const float*)d_in[18],*l1bias=(const float*)d_in[19];
    const float* l1g=(const float*)d_in[20],  *l1be=(const float*)d_in[21];
    const float* mw1=(const float*)d_in[22],  *mb1=(const float*)d_in[23];
    const float* mw2=(const float*)d_in[24],  *mb2=(const float*)d_in[25];
    float* out = (float*)d_out;

    int dev = 0;
    cudaGetDevice(&dev);
    int nsm = 0;
    cudaDeviceGetAttribute(&nsm, cudaDevAttrMultiProcessorCount, dev);
    if (nsm <= 0) nsm = 148;
    int nb = 0;
    cudaOccupancyMaxActiveBlocksPerMultiprocessor(&nb, k_mega, TPB, 0);
    if (nb < 1) nb = 1;
    int grid = nsm * nb;
    if (grid > 1024) grid = 1024;

    k_mega<<<grid, TPB>>>(x, attr, edft, src, dst, batch,
                          l0w1, l0b1, l0w2, l0b2, l0root, l0bias, l0g, l0be,
                          l1w1, l1b1, l1w2, l1b2, l1root, l1bias, l1g, l1be,
                          mw1, mb1, mw2, mb2, out);
}

// round 17
// speedup vs baseline: 1.1206x; 1.1206x over previous
#include <cuda_runtime.h>
#include <cfloat>

#define Nn 20000
#define Ee 320000
#define Gg 64
#define D0 16
#define Hh 32
#define NK 33
#define EPSI 1e-5f
#define FULL 0xffffffffu
#define TPB 1024

// ---------------- static device scratch (zero-init at load; self-cleaning across replays) ----------------
__device__ float g_A0[NK*D0*Hh], g_B0[NK*D0*Hh];
__device__ float g_A1[NK*Hh*Hh], g_B1[NK*Hh*Hh];
__device__ int g_deg[Nn];               // zeroed in alloc phase after read
__device__ int g_rank[Ee];              // per-edge rank within its dst segment
__device__ int g_total;                 // zeroed in final phase each run
__device__ int g_off[Nn], g_end[Nn];
__device__ int g_nlive[2], g_klive[2];
__device__ float g_bmin[1024], g_bmax[1024];
__device__ uint2 g_ebuf[Ee];
__device__ __align__(16) float g_PQ[(size_t)NK*Nn*64];   // general path only
__device__ __align__(16) float g_h[Nn*Hh], g_hn[Nn*Hh];
__device__ float g_stats[4*Hh];
__device__ float g_pool[Gg*Hh];
__device__ int   g_pcnt[Gg];
__device__ int g_bcnt[8];
__device__ volatile int g_bsense[8];

__device__ __forceinline__ void gridbar(int i){
    __syncthreads();
    if (threadIdx.x == 0){
        int sense = g_bsense[i];
        __threadfence();
        if (atomicAdd(&g_bcnt[i], 1) == (int)gridDim.x - 1){
            g_bcnt[i] = 0;
            __threadfence();
            g_bsense[i] = sense ^ 1;
        } else {
            while (g_bsense[i] == sense) __nanosleep(64);
            __threadfence();
        }
    }
    __syncthreads();
}

__device__ __forceinline__ void rank32(float wj, float bj, float& t, int& r, int j){
    t = (wj != 0.0f) ? (-bj / wj) : FLT_MAX;
    r = 0;
    #pragma unroll
    for (int m = 0; m < 32; m++){
        float tm = __shfl_sync(FULL, t, m);
        r += (tm < t || (tm == t && m < j));
    }
}

// ==== aggregation phase: fast path pipelined across nodes (incl. x-row prefetch) ====
template<int DIN, int LAYER>
__device__ __forceinline__ void agg_phase(
    const float* __restrict__ xin, const float* __restrict__ root,
    const float* __restrict__ bias, float* __restrict__ hout,
    float* sA, float* sB, float* sR, float* sBi,
    float* ssum, float* ssq, float (*sAcc)[64], int nlive, int kl)
{
    constexpr int NC = DIN/4;
    constexpr int NS = 32/NC;
    int t = threadIdx.x, lane = t & 31, w = t >> 5;
    __syncthreads();
    if (t < 32){ ssum[t] = 0.f; ssq[t] = 0.f; sBi[t] = __ldg(bias + t); }
    for (int d = t; d < DIN*32; d += TPB) sR[d] = __ldg(root + d);
    if (nlive == 1){
        const float* A = LAYER ? g_A1 : g_A0;
        const float* B = LAYER ? g_B1 : g_B0;
        for (int d = t; d < DIN*32; d += TPB){
            sA[d] = A[kl*DIN*32 + d];
            sB[d] = B[kl*DIN*32 + d];
        }
    }
    __syncthreads();

    const float4* x4 = (const float4*)xin;
    float accS = 0.f, accQ = 0.f;
    int stride = gridDim.x*32;

    if (nlive == 1){
        int slot = lane / NC, c = lane % NC;
        int v = blockIdx.x*32 + w;
        int s = 0, e1 = 0;
        float xvv = 0.f;
        bool v0 = false, v1 = false;
        uint2 p0 = make_uint2(0,0), p1 = make_uint2(0,0);
        if (v < Nn){
            s = g_off[v]; e1 = g_end[v];
            if (lane < DIN) xvv = xin[(size_t)v*DIN + lane];
            int i0 = s + slot, i1 = i0 + NS;
            v0 = i0 < e1; v1 = i1 < e1;
            if (v0) p0 = __ldcg(&g_ebuf[i0]);
            if (v1) p1 = __ldcg(&g_ebuf[i1]);
        }
        while (v < Nn){
            // prefetch next node's bounds + x row (resolve behind gather+epilogue)
            int nv = v + stride;
            int ns = 0, ne = 0;
            float nxv = 0.f;
            if (nv < Nn){
                ns = g_off[nv]; ne = g_end[nv];
                if (lane < DIN) nxv = xin[(size_t)nv*DIN + lane];
            }

            float4 ya0={0,0,0,0}, yb0={0,0,0,0}, ya1={0,0,0,0}, yb1={0,0,0,0};
            int c0 = s + slot, c1 = c0 + NS;
            while (__any_sync(FULL, v0)){
                int n0 = c0 + 2*NS, n1 = c1 + 2*NS;
                bool w0 = n0 < e1, w1 = n1 < e1;
                uint2 q0 = make_uint2(0,0), q1 = make_uint2(0,0);
                if (w0) q0 = __ldcg(&g_ebuf[n0]);
                if (w1) q1 = __ldcg(&g_ebuf[n1]);
                if (v0){
                    int u = p0.x & 0xFFFF; float a = __uint_as_float(p0.y);
                    float4 xc = x4[(size_t)u*NC + c];
                    ya0.x = fmaf(a, xc.x, ya0.x); yb0.x += xc.x;
                    ya0.y = fmaf(a, xc.y, ya0.y); yb0.y += xc.y;
                    ya0.z = fmaf(a, xc.z, ya0.z); yb0.z += xc.z;
                    ya0.w = fmaf(a, xc.w, ya0.w); yb0.w += xc.w;
                }
                if (v1){
                    int u = p1.x & 0xFFFF; float a = __uint_as_float(p1.y);
                    float4 xc = x4[(size_t)u*NC + c];
                    ya1.x = fmaf(a, xc.x, ya1.x); yb1.x += xc.x;
                    ya1.y = fmaf(a, xc.y, ya1.y); yb1.y += xc.y;
                    ya1.z = fmaf(a, xc.z, ya1.z); yb1.z += xc.z;
                    ya1.w = fmaf(a, xc.w, ya1.w); yb1.w += xc.w;
                }
                c0 = n0; c1 = n1; v0 = w0; v1 = w1; p0 = q0; p1 = q1;
            }

            // prefetch next node's first payloads (resolve behind reduction+epilogue)
            int ni0 = ns + slot, ni1 = ni0 + NS;
            bool nv0 = (nv < Nn) && (ni0 < ne);
            bool nv1 = (nv < Nn) && (ni1 < ne);
            uint2 np0 = make_uint2(0,0), np1 = make_uint2(0,0);
            if (nv0) np0 = __ldcg(&g_ebuf[ni0]);
            if (nv1) np1 = __ldcg(&g_ebuf[ni1]);

            float4 ya, yb;
            ya.x = ya0.x + ya1.x; ya.y = ya0.y + ya1.y;
            ya.z = ya0.z + ya1.z; ya.w = ya0.w + ya1.w;
            yb.x = yb0.x + yb1.x; yb.y = yb0.y + yb1.y;
            yb.z = yb0.z + yb1.z; yb.w = yb0.w + yb1.w;
            #pragma unroll
            for (int off = NC; off < 32; off <<= 1){
                ya.x += __shfl_xor_sync(FULL, ya.x, off);
                ya.y += __shfl_xor_sync(FULL, ya.y, off);
                ya.z += __shfl_xor_sync(FULL, ya.z, off);
                ya.w += __shfl_xor_sync(FULL, ya.w, off);
                yb.x += __shfl_xor_sync(FULL, yb.x, off);
                yb.y += __shfl_xor_sync(FULL, yb.y, off);
                yb.z += __shfl_xor_sync(FULL, yb.z, off);
                yb.w += __shfl_xor_sync(FULL, yb.w, off);
            }
            if (lane < NC){
                int f = lane*4;
                sAcc[w][f+0] = ya.x; sAcc[w][f+1] = ya.y;
                sAcc[w][f+2] = ya.z; sAcc[w][f+3] = ya.w;
                sAcc[w][DIN+f+0] = yb.x; sAcc[w][DIN+f+1] = yb.y;
                sAcc[w][DIN+f+2] = yb.z; sAcc[w][DIN+f+3] = yb.w;
            }
            __syncwarp();
            float msg = 0.f;
            #pragma unroll
            for (int i = 0; i < DIN; i++){
                msg = fmaf(sAcc[w][i],     sA[i*32+lane], msg);
                msg = fmaf(sAcc[w][DIN+i], sB[i*32+lane], msg);
            }
            float inv = 1.f / fmaxf((float)(e1 - s), 1.f);
            float rt = 0.f;
            #pragma unroll
            for (int i = 0; i < DIN; i++)
                rt = fmaf(__shfl_sync(FULL, xvv, i), sR[i*32+lane], rt);
            float o = rt + msg*inv + sBi[lane];
            hout[(size_t)v*32 + lane] = o;
            accS += o;
            accQ = fmaf(o, o, accQ);

            v = nv; s = ns; e1 = ne; xvv = nxv; v0 = nv0; v1 = nv1; p0 = np0; p1 = np1;
        }
    } else {
        int slot = lane >> 3, c = lane & 7;
        int shift = 16 + (LAYER << 3);
        for (int v = blockIdx.x*32 + w; v < Nn; v += stride){
            int s = g_off[v], e1 = g_end[v];
            float4 acc = {0,0,0,0};
            for (int base = s; base < e1; base += 4){
                int i = base + slot;
                if (i < e1){
                    uint2 pl = __ldcg(&g_ebuf[i]);
                    int u = pl.x & 0xFFFF; int kk = (pl.x >> shift) & 0xFF;
                    float a = __uint_as_float(pl.y);
                    const float4* row = (const float4*)(g_PQ + ((size_t)(kk*Nn + u))*64);
                    float4 p = row[c], q = row[8+c];
                    acc.x = fmaf(a, p.x, acc.x) + q.x;
                    acc.y = fmaf(a, p.y, acc.y) + q.y;
                    acc.z = fmaf(a, p.z, acc.z) + q.z;
                    acc.w = fmaf(a, p.w, acc.w) + q.w;
                }
            }
            #pragma unroll
            for (int off = 8; off < 32; off <<= 1){
                acc.x += __shfl_xor_sync(FULL, acc.x, off);
                acc.y += __shfl_xor_sync(FULL, acc.y, off);
                acc.z += __shfl_xor_sync(FULL, acc.z, off);
                acc.w += __shfl_xor_sync(FULL, acc.w, off);
            }
            if (lane < 8){
                int f = lane*4;
                sAcc[w][f+0] = acc.x; sAcc[w][f+1] = acc.y;
                sAcc[w][f+2] = acc.z; sAcc[w][f+3] = acc.w;
            }
            __syncwarp();
            float msg = sAcc[w][lane];
            float inv = 1.f / fmaxf((float)(e1 - s), 1.f);
            float xv = (lane < DIN) ? xin[(size_t)v*DIN + lane] : 0.f;
            float rt = 0.f;
            #pragma unroll
            for (int i = 0; i < DIN; i++)
                rt = fmaf(__shfl_sync(FULL, xv, i), sR[i*32+lane], rt);
            float o = rt + msg*inv + sBi[lane];
            hout[(size_t)v*32 + lane] = o;
            accS += o;
            accQ = fmaf(o, o, accQ);
        }
    }
    atomicAdd(&ssum[lane], accS);
    atomicAdd(&ssq[lane], accQ);
    __syncthreads();
    if (t < 32){
        atomicAdd(&g_stats[LAYER*64 + t],      ssum[t]);
        atomicAdd(&g_stats[LAYER*64 + 32 + t], ssq[t]);
    }
}

// ==== single persistent mega-kernel ====
__global__ void __launch_bounds__(TPB, 1)
k_mega(const float* __restrict__ x, const float* __restrict__ attr,
       const float* __restrict__ edft, const int* __restrict__ src,
       const int* __restrict__ dst, const int* __restrict__ batch,
       const float* l0w1, const float* l0b1, const float* l0w2, const float* l0b2,
       const float* l0root, const float* l0bias, const float* l0g, const float* l0be,
       const float* l1w1, const float* l1b1, const float* l1w2, const float* l1b2,
       const float* l1root, const float* l1bias, const float* l1g, const float* l1be,
       const float* mw1, const float* mb1, const float* mw2, const float* mb2,
       float* out)
{
    __shared__ float sW0[1024], sW1[1024], sW2[1024];
    __shared__ float sSc[32], sSh[32], sBi[32], ssum[32], ssq[32];
    __shared__ float sMin[32], sMax[32];
    __shared__ float sAcc[32][64];
    int t = threadIdx.x, lane = t & 31, w = t >> 5;

    // -------- P0: zeroing (block 0) + buildAB (blocks <2NK) + edge deg/rank/minmax (all) --------
    if (blockIdx.x == 0){
        for (int i = t; i < 4*Hh; i += TPB) g_stats[i] = 0.f;
        for (int i = t; i < Gg*Hh; i += TPB) g_pool[i] = 0.f;
        if (t < Gg) g_pcnt[t] = 0;
    }
    if (blockIdx.x < 2*NK){
        int layer = (blockIdx.x >= NK);
        int k = blockIdx.x - layer*NK;
        int D = layer ? (Hh*Hh) : (D0*Hh);
        float* A = layer ? g_A1 : g_A0;
        float* B = layer ? g_B1 : g_B0;
        const float* ew1 = layer ? l1w1 : l0w1;
        const float* eb1 = layer ? l1b1 : l0b1;
        const float* ew2 = layer ? l1w2 : l0w2;
        const float* eb2 = layer ? l1b2 : l0b2;
        float* sw = sW0; float* sb = sW0 + 32; int* sr = (int*)sW1;
        if (t < 32){
            float wj = ew1[t], bj = eb1[t], tv; int r;
            rank32(wj, bj, tv, r, t);
            sw[t] = wj; sb[t] = bj; sr[t] = r;
        }
        __syncthreads();
        for (int d = t; d < D; d += TPB){
            float a = 0.f, b = eb2[d];
            for (int j = 0; j < 32; j++){
                float wj = sw[j];
                bool act = (wj > 0.f) ? (k > sr[j]) : ((wj < 0.f) ? (k <= sr[j]) : (sb[j] > 0.f));
                if (act){ float w2 = ew2[j*D+d]; a += wj*w2; b += sb[j]*w2; }
            }
            A[k*D+d] = a; B[k*D+d] = b;
        }
        __syncthreads();
    }
    {
        float amn = FLT_MAX, amx = -FLT_MAX;
        for (int e = blockIdx.x*TPB + t; e < Ee; e += gridDim.x*TPB){
            float a = attr[e];
            amn = fminf(amn, a); amx = fmaxf(amx, a);
            g_rank[e] = atomicAdd(&g_deg[dst[e]], 1);
        }
        #pragma unroll
        for (int off = 16; off; off >>= 1){
            amn = fminf(amn, __shfl_xor_sync(FULL, amn, off));
            amx = fmaxf(amx, __shfl_xor_sync(FULL, amx, off));
        }
        if (lane == 0){ sMin[w] = amn; sMax[w] = amx; }
        __syncthreads();
        if (t < 32){
            amn = sMin[t]; amx = sMax[t];
            #pragma unroll
            for (int off = 16; off; off >>= 1){
                amn = fminf(amn, __shfl_xor_sync(FULL, amn, off));
                amx = fmaxf(amx, __shfl_xor_sync(FULL, amx, off));
            }
            if (t == 0){ g_bmin[blockIdx.x] = amn; g_bmax[blockIdx.x] = amx; }
        }
    }
    gridbar(0);

    // -------- P1: segment allocation + interval-range detect --------
    if (blockIdx.x == 0 && t < 32){
        float amn = FLT_MAX, amx = -FLT_MAX;
        for (int b = lane; b < (int)gridDim.x; b += 32){
            amn = fminf(amn, g_bmin[b]); amx = fmaxf(amx, g_bmax[b]);
        }
        #pragma unroll
        for (int off = 16; off; off >>= 1){
            amn = fminf(amn, __shfl_xor_sync(FULL, amn, off));
            amx = fmaxf(amx, __shfl_xor_sync(FULL, amx, off));
        }
        float wj = l0w1[lane], bj = l0b1[lane];
        float tj = (wj != 0.f) ? (-bj/wj) : FLT_MAX;
        int kmin = __popc(__ballot_sync(FULL, tj <= amn));
        int kmax = __popc(__ballot_sync(FULL, tj <= amx));
        if (lane == 0){ g_klive[0] = kmin; g_nlive[0] = kmax - kmin + 1; }
        wj = l1w1[lane]; bj = l1b1[lane];
        tj = (wj != 0.f) ? (-bj/wj) : FLT_MAX;
        kmin = __popc(__ballot_sync(FULL, tj <= amn));
        kmax = __popc(__ballot_sync(FULL, tj <= amx));
        if (lane == 0){ g_klive[1] = kmin; g_nlive[1] = kmax - kmin + 1; }
    }
    for (int base = blockIdx.x*TPB; base < Nn; base += gridDim.x*TPB){
        int i = base + t;
        int d = (i < Nn) ? g_deg[i] : 0;
        int sc = d;
        #pragma unroll
        for (int off = 1; off < 32; off <<= 1){
            int y = __shfl_up_sync(FULL, sc, off);
            if (lane >= off) sc += y;
        }
        int tot = __shfl_sync(FULL, sc, 31);
        int base2 = 0;
        if (lane == 31 && tot) base2 = atomicAdd(&g_total, tot);
        base2 = __shfl_sync(FULL, base2, 31);
        if (i < Nn){
            int my = base2 + sc - d;
            g_off[i] = my; g_end[i] = my + d;
            g_deg[i] = 0;
        }
    }
    gridbar(1);

    int nl0 = g_nlive[0], kl0 = g_klive[0];
    int nl1 = g_nlive[1], kl1 = g_klive[1];
    bool fastboth = (nl0 == 1) && (nl1 == 1);

    // -------- P2: CSR fill (rank-based, no atomics) + PQ0 (general) --------
    if (!fastboth){
        float* st0 = sW0; float* st1 = sW0 + 32;
        if (t < 32){ float tv; int r; rank32(l0w1[t], l0b1[t], tv, r, t); st0[r] = tv; }
        else if (t < 64){ int j = t-32; float tv; int r; rank32(l1w1[j], l1b1[j], tv, r, j); st1[r] = tv; }
        __syncthreads();
    }
    for (int e = blockIdx.x*TPB + t; e < Ee; e += gridDim.x*TPB){
        float a = attr[e];
        unsigned px = (unsigned)src[e];
        if (!fastboth){
            const float* st0 = sW0; const float* st1 = sW0 + 32;
            int k0 = 0, k1 = 0;
            #pragma unroll
            for (int step = 16; step > 0; step >>= 1){
                if (st0[k0 + step - 1] <= a) k0 += step;
                if (st1[k1 + step - 1] <= a) k1 += step;
            }
            k0 += (st0[k0] <= a);
            k1 += (st1[k1] <= a);
            px |= ((unsigned)k0 << 16) | ((unsigned)k1 << 24);
        }
        uint2 pl; pl.x = px; pl.y = __float_as_uint(a);
        int p = g_off[dst[e]] + g_rank[e];
        g_ebuf[p] = pl;
    }
    if (nl0 > 1){
        for (int u = blockIdx.x*32 + w; u < Nn; u += gridDim.x*32){
            float xv_l = (lane < D0) ? __ldg(x + (size_t)u*D0 + lane) : 0.f;
            for (int k = kl0; k < kl0 + nl0; k++){
                float p = 0.f, q = 0.f;
                for (int i = 0; i < D0; i++){
                    float xv = __shfl_sync(FULL, xv_l, i);
                    p = fmaf(xv, g_A0[k*D0*Hh + i*Hh + lane], p);
                    q = fmaf(xv, g_B0[k*D0*Hh + i*Hh + lane], q);
                }
                size_t ro = ((size_t)(k*Nn + u))*64;
                g_PQ[ro + lane] = p;
                g_PQ[ro + 32 + lane] = q;
            }
        }
    }
    gridbar(2);

    // -------- P3: aggregation layer 0 --------
    agg_phase<D0,0>(x, l0root, l0bias, g_h,
                    sW0, sW1, sW2, sBi, ssum, ssq, sAcc, nl0, kl0);
    gridbar(3);

    // -------- P3a: hn = relu(BN0(h)) once --------
    __syncthreads();
    if (t < 32){
        float mu  = __ldcg(&g_stats[t])    * (1.f/(float)Nn);
        float var = __ldcg(&g_stats[32+t]) * (1.f/(float)Nn) - mu*mu;
        float sc  = rsqrtf(var + EPSI) * __ldg(l0g + t);
        sSc[t] = sc;
        sSh[t] = __ldg(l0be + t) - mu*sc;
    }
    __syncthreads();
    for (int idx = blockIdx.x*TPB + t; idx < Nn*Hh; idx += gridDim.x*TPB){
        int f = idx & 31;
        g_hn[idx] = fmaxf(g_h[idx]*sSc[f] + sSh[f], 0.f);
    }
    gridbar(4);
    if (nl1 > 1){
        for (int u = blockIdx.x*32 + w; u < Nn; u += gridDim.x*32){
            float xv_l = g_hn[(size_t)u*32 + lane];
            for (int k = kl1; k < kl1 + nl1; k++){
                float p = 0.f, q = 0.f;
                for (int i = 0; i < Hh; i++){
                    float xv = __shfl_sync(FULL, xv_l, i);
                    p = fmaf(xv, g_A1[k*Hh*Hh + i*Hh + lane], p);
                    q = fmaf(xv, g_B1[k*Hh*Hh + i*Hh + lane], q);
                }
                size_t ro = ((size_t)(k*Nn + u))*64;
                g_PQ[ro + lane] = p;
                g_PQ[ro + 32 + lane] = q;
            }
        }
        gridbar(5);
    }

    // -------- P4: aggregation layer 1 --------
    agg_phase<Hh,1>(g_hn, l1root, l1bias, g_h,
                    sW0, sW1, sW2, sBi, ssum, ssq, sAcc, nl1, kl1);
    gridbar(6);

    // -------- P5: BN1 + ReLU + pool --------
    __syncthreads();
    if (t < 32){
        float mu  = __ldcg(&g_stats[64+t]) * (1.f/(float)Nn);
        float var = __ldcg(&g_stats[96+t]) * (1.f/(float)Nn) - mu*mu;
        float sc  = rsqrtf(var + EPSI) * __ldg(l1g + t);
        sSc[t] = sc;
        sSh[t] = __ldg(l1be + t) - mu*sc;
    }
    __syncthreads();
    for (int idx = blockIdx.x*TPB + t; idx < Nn*Hh; idx += gridDim.x*TPB){
        int f = idx & 31, v = idx >> 5;
        float xv = fmaxf(g_h[idx]*sSc[f] + sSh[f], 0.f);
        int g = batch[v];
        atomicAdd(&g_pool[g*Hh + f], xv);
        if (f == 0) atomicAdd(&g_pcnt[g], 1);
    }
    gridbar(7);

    // -------- P6: readout MLP + cleanup (block 0) --------
    if (blockIdx.x == 0){
        if (t == TPB-1) g_total = 0;
        if (t < Gg){
            float zin[Hh+1];
            float inv = 1.f / fmaxf((float)__ldcg(&g_pcnt[t]), 1.f);
            for (int i = 0; i < Hh; i++) zin[i] = __ldcg(&g_pool[t*Hh+i])*inv;
            zin[Hh] = edft[t];
            float o = mb2[0];
            for (int j = 0; j < 64; j++){
                float hsum = mb1[j];
                #pragma unroll
                for (int i = 0; i < Hh+1; i++) hsum = fmaf(zin[i], mw1[i*64+j], hsum);
                o = fmaf(fmaxf(hsum, 0.f), mw2[j], o);
            }
            out[t] = o;
        }
    }
}

extern "C" void kernel_launch(void* const* d_in, const int* in_sizes, int n_in,
                              void* d_out, int out_size){
    const float* x     = (const float*)d_in[0];
    const float* attr  = (const float*)d_in[1];
    const float* edft  = (const float*)d_in[2];
    const int*   src   = (const int*)  d_in[3];
    const int*   dst   = (const int*)  d_in[4];
    const int*   batch = (const int*)  d_in[5];
    const float* l0w1=(const float*)d_in[6],  *l0b1=(const float*)d_in[7];
    const float* l0w2=(const float*)d_in[8],  *l0b2=(const float*)d_in[9];
    const float* l0root=(const float*)d_in[10],*l0bias=(const float*)d_in[11];
    const float* l0g=(const float*)d_in[12],  *l0be=(const float*)d_in[13];
    const float* l1w1=(const float*)d_in[14], *l1b1=(const float*)d_in[15];
    const float* l1w2=(const float*)d_in[16], *l1b2=(const float*)d_in[17];
    const float* l1root=(const float*)d_in[18],*l1bias=(const float*)d_in[19];
    const float* l1g=(const float*)d_in[20],  *l1be=(const float*)d_in[21];
    const float* mw1=(const float*)d_in[22],  *mb1=(const float*)d_in[23];
    const float* mw2=(const float*)d_in[24],  *mb2=(const float*)d_in[25];
    float* out = (float*)d_out;

    int dev = 0;
    cudaGetDevice(&dev);
    int nsm = 0;
    cudaDeviceGetAttribute(&nsm, cudaDevAttrMultiProcessorCount, dev);
    if (nsm <= 0) nsm = 148;
    int nb = 0;
    cudaOccupancyMaxActiveBlocksPerMultiprocessor(&nb, k_mega, TPB, 0);
    if (nb < 1) nb = 1;
    int grid = nsm * nb;
    if (grid > 1024) grid = 1024;

    k_mega<<<grid, TPB>>>(x, attr, edft, src, dst, batch,
                          l0w1, l0b1, l0w2, l0b2, l0root, l0bias, l0g, l0be,
                          l1w1, l1b1, l1w2, l1b2, l1root, l1bias, l1g, l1be,
                          mw1, mb1, mw2, mb2, out);
}